// round 14
// baseline (speedup 1.0000x reference)
#include <cuda_runtime.h>
#include <cstdint>

#define KTAG 64
#define BTOT 1024
#define TLEN 512
#define START_TAG 62
#define FWD_GRID (BTOT / 4)   // 256 blocks x 4 warps = 1024 rows

// Scratch (allocation-free rule: __device__ globals)
__device__ float g_res[BTOT];   // forward_score[b] - gold_score[b]
__device__ int   g_cnt = 0;

typedef unsigned long long ull;

__device__ __forceinline__ ull pk2(float x, float y) {
    return (ull)__float_as_uint(x) | ((ull)__float_as_uint(y) << 32);
}
__device__ __forceinline__ float lo2(ull v) { return __uint_as_float((unsigned)v); }
__device__ __forceinline__ float hi2(ull v) { return __uint_as_float((unsigned)(v >> 32)); }
__device__ __forceinline__ float rcpf(float x) {
    float r; asm("rcp.approx.f32 %0, %1;" : "=f"(r) : "f"(x)); return r;
}

#define FMA2(acc, a, b) asm("fma.rn.f32x2 %0, %1, %2, %0;" : "+l"(acc) : "l"(a), "l"(b))
#define ADD2(d, a, b)   asm("add.rn.f32x2 %0, %1, %2;" : "=l"(d) : "l"(a), "l"(b))
#define MUL2(d, a, b)   asm("mul.rn.f32x2 %0, %1, %2;" : "=l"(d) : "l"(a), "l"(b))
// zero-instruction compiler barrier: keeps the STS -> next-step LDS order in
// the compiler; HW order is guaranteed by same-address smem dependencies and
// warp lockstep (the loop body is convergence-free).
#define CBAR()          asm volatile("" ::: "memory")

// ---------------------------------------------------------------------------
// Fully fused CRF kernel (R13 base) + serial-tail trim:
//  - per-step __syncwarp removed (loop is fully convergent: all branches are
//    uniform or compile-time; gold uses a predicated add, not a branch);
//  - gold feat term accumulated by the OWNING lane (predicated add) instead
//    of a per-step shfl broadcast; single 5-shfl reduce at the end.
// One warp per batch row; lane l owns tags 2l,2l+1 + E-rows in 124 regs;
// deferred normalization by u = w[0] every 4th step (exact bookkeeping);
// 4-deep feat prefetch (MLP=4); zero pair (62,63) skipped; trans + tags in
// smem; last-block mean with the R11-validated ordering fix.
// ---------------------------------------------------------------------------
__global__ void __launch_bounds__(128, 2)
crf_fused_kernel(const float* __restrict__ feats,
                 const int* __restrict__ tags,
                 const float* __restrict__ trans,
                 float* __restrict__ out) {
    const int lane = threadIdx.x & 31;
    const int w    = threadIdx.x >> 5;          // row within CTA (0..3)
    const int b    = blockIdx.x * 4 + w;
    const int i0   = 2 * lane;
    const int i1   = 2 * lane + 1;

    __shared__ __align__(16) float         sw_[4][2][KTAG];
    __shared__ __align__(16) float         strans[KTAG * KTAG];   // 16 KB
    __shared__ __align__(16) unsigned char stagsu[4][TLEN];       // 2 KB

    // copy trans to smem (float4 coalesced, whole CTA)
    {
        const float4* t4 = (const float4*)trans;
        float4* s4 = (float4*)strans;
#pragma unroll
        for (int j = threadIdx.x; j < (KTAG * KTAG) / 4; j += 128) s4[j] = t4[j];
    }

    // cache this row's tags as uint8 (int4 coalesced loads)
    {
        const int4* tg4 = (const int4*)(tags + (size_t)b * TLEN);
        uchar4* st4 = (uchar4*)stagsu[w];
#pragma unroll
        for (int j = lane; j < TLEN / 4; j += 32) {
            int4 v = tg4[j];
            st4[j] = make_uchar4((unsigned char)v.x, (unsigned char)v.y,
                                 (unsigned char)v.z, (unsigned char)v.w);
        }
    }

    // E rows for tags i0, i1 (f32x2 packed over j); pair jj=31 skipped
    ull E0[31], E1[31];
#pragma unroll
    for (int jj = 0; jj < 31; jj++) {
        E0[jj] = pk2(__expf(trans[i0 * KTAG + 2 * jj]),
                     __expf(trans[i0 * KTAG + 2 * jj + 1]));
        E1[jj] = pk2(__expf(trans[i1 * KTAG + 2 * jj]),
                     __expf(trans[i1 * KTAG + 2 * jj + 1]));
    }

    const float* fb = feats + (size_t)b * TLEN * KTAG;

    // t = 1 exact: w1 = exp(trans[:,START] + feat1)
    float2 f1 = *(const float2*)(fb + 1 * KTAG + i0);
    float a0 = trans[i0 * KTAG + START_TAG] + f1.x;
    float a1 = trans[i1 * KTAG + START_TAG] + f1.y;
    *(float2*)&sw_[w][0][i0] = make_float2(__expf(a0), __expf(a1));
    float L = 0.0f;
    __syncthreads();                              // strans + stags + w1 visible

    // gold accumulators: goldt = trans terms (uniform on all lanes),
    // goldf = feat terms owned by this lane (ct>>1 == lane)
    int   pt = stagsu[w][0];
    float goldt, goldf;
    {
        int ct = stagsu[w][1];
        float gs = (ct & 1) ? f1.y : f1.x;
        goldt = strans[ct * KTAG + pt];
        goldf = ((ct >> 1) == lane) ? gs : 0.0f;
        pt = ct;
    }

    // 4-deep feat pipeline: F[k] = feat(t = 2+k) raw
    float2 F[4];
#pragma unroll
    for (int k = 0; k < 4; k++)
        F[k] = *(const float2*)(fb + (size_t)(2 + k) * KTAG + i0);

    // gold accumulation for step T: uniform trans add + owner-lane feat add
#define GOLD_ACC(T, FX, FY)                                                   \
    {                                                                         \
        int ct = stagsu[w][(T)];                                              \
        goldt += strans[ct * KTAG + pt];                                      \
        float gs = (ct & 1) ? (FY) : (FX);                                    \
        if ((ct >> 1) == lane) goldf += gs;                                   \
        pt = ct;                                                              \
    }

    // one recurrence step; NORM = 1 -> renormalize by u = w[0]
#define STEP_BODY(T, EFC0, EFC1, NORM)                                        \
    {                                                                         \
        const int rbuf = (T) & 1;                                             \
        const ulonglong2* vp = (const ulonglong2*)sw_[w][rbuf];               \
        ulonglong2 v0 = vp[0];                                                \
        ull c0 = 0, c1 = 0, c2 = 0, c3 = 0;                                   \
        ull d0 = 0, d1 = 0, d2 = 0, d3 = 0;                                   \
        FMA2(c0, E0[0], v0.x); FMA2(c1, E0[1], v0.y);                         \
        FMA2(d0, E1[0], v0.x); FMA2(d1, E1[1], v0.y);                         \
        _Pragma("unroll")                                                     \
        for (int q = 1; q < 16; q++) {                                        \
            ulonglong2 vv = vp[q];                                            \
            if (q == 15) {            /* pair (62,63) contributes zero */     \
                FMA2(c2, E0[30], vv.x);                                       \
                FMA2(d2, E1[30], vv.x);                                       \
            } else if (q & 1) {                                               \
                FMA2(c2, E0[2 * q], vv.x); FMA2(c3, E0[2 * q + 1], vv.y);     \
                FMA2(d2, E1[2 * q], vv.x); FMA2(d3, E1[2 * q + 1], vv.y);     \
            } else {                                                          \
                FMA2(c0, E0[2 * q], vv.x); FMA2(c1, E0[2 * q + 1], vv.y);     \
                FMA2(d0, E1[2 * q], vv.x); FMA2(d1, E1[2 * q + 1], vv.y);     \
            }                                                                 \
        }                                                                     \
        ull cA, cB, cs, dA, dB, ds, sp, sq, sv2, mm, wn;                      \
        ADD2(cA, c0, c2); ADD2(cB, c1, c3); ADD2(cs, cA, cB);                 \
        ADD2(dA, d0, d2); ADD2(dB, d1, d3); ADD2(ds, dA, dB);                 \
        sp = pk2(lo2(cs), lo2(ds));                                           \
        sq = pk2(hi2(cs), hi2(ds));                                           \
        ADD2(sv2, sp, sq);                        /* (s0, s1) packed */       \
        if (NORM) {                                                           \
            float uu = lo2(v0.x);                                             \
            float r  = rcpf(uu);                                              \
            L += __logf(uu);                                                  \
            mm = pk2((EFC0) * r, (EFC1) * r);                                 \
        } else {                                                              \
            mm = pk2((EFC0), (EFC1));                                         \
        }                                                                     \
        MUL2(wn, sv2, mm);                                                    \
        *(ull*)&sw_[w][rbuf ^ 1][i0] = wn;                                    \
        CBAR();                                                               \
    }

    // main loop: t = 2 .. 509, 127 blocks of 4 (MLP=4); norm at k == 3
    for (int kb = 0; kb < 127; kb++) {
#pragma unroll
        for (int k = 0; k < 4; k++) {
            const int t = 2 + 4 * kb + k;
            float fx = F[k].x, fy = F[k].y;
            GOLD_ACC(t, fx, fy)
            float efc0 = __expf(fx);
            float efc1 = __expf(fy);
            int tn = t + 4; if (tn > TLEN - 1) tn = TLEN - 1;
            F[k] = *(const float2*)(fb + (size_t)tn * KTAG + i0);
            if (k == 3) { STEP_BODY(t, efc0, efc1, 1) }
            else        { STEP_BODY(t, efc0, efc1, 0) }
        }
    }

    // t = 510 (feat in F[0])
    {
        float fx = F[0].x, fy = F[0].y;
        GOLD_ACC(510, fx, fy)
        float efc0 = __expf(fx);
        float efc1 = __expf(fy);
        STEP_BODY(510, efc0, efc1, 0)
    }

    // final step t = 511 (feat in F[1]): forward = L + log(sum_i s_i*exp(f_i))
    {
        float fx = F[1].x, fy = F[1].y;
        GOLD_ACC(511, fx, fy)
        float ef0 = __expf(fx);
        float ef1 = __expf(fy);
        const int rbuf = (TLEN - 1) & 1;
        const ulonglong2* vp = (const ulonglong2*)sw_[w][rbuf];
        ull c0 = 0, c1 = 0, c2 = 0, c3 = 0;
        ull d0 = 0, d1 = 0, d2 = 0, d3 = 0;
#pragma unroll
        for (int q = 0; q < 16; q++) {
            ulonglong2 vv = vp[q];
            if (q == 15) {
                FMA2(c2, E0[30], vv.x);
                FMA2(d2, E1[30], vv.x);
            } else if (q & 1) {
                FMA2(c2, E0[2 * q], vv.x); FMA2(c3, E0[2 * q + 1], vv.y);
                FMA2(d2, E1[2 * q], vv.x); FMA2(d3, E1[2 * q + 1], vv.y);
            } else {
                FMA2(c0, E0[2 * q], vv.x); FMA2(c1, E0[2 * q + 1], vv.y);
                FMA2(d0, E1[2 * q], vv.x); FMA2(d1, E1[2 * q + 1], vv.y);
            }
        }
        ull cA, cB, cs, dA, dB, ds;
        ADD2(cA, c0, c2); ADD2(cB, c1, c3); ADD2(cs, cA, cB);
        ADD2(dA, d0, d2); ADD2(dB, d1, d3); ADD2(ds, dA, dB);
        float s0 = lo2(cs) + hi2(cs);
        float s1 = lo2(ds) + hi2(ds);
        float z = s0 * ef0 + s1 * ef1;
        float gf = goldf;
#pragma unroll
        for (int o = 16; o > 0; o >>= 1) {
            z  += __shfl_xor_sync(0xffffffffu, z,  o);
            gf += __shfl_xor_sync(0xffffffffu, gf, o);
        }
        if (lane == 0) g_res[b] = (L + __logf(z)) - (goldt + gf);
    }
#undef STEP_BODY
#undef GOLD_ACC

    // ---- last-block mean reduction (R11-validated ordering) ----
    // per-warp g_res stores -> __threadfence (every thread) -> __syncthreads
    // -> atomic counter. Counter self-resets for graph replay.
    __threadfence();
    __syncthreads();
    __shared__ int is_last;
    if (threadIdx.x == 0) {
        int old = atomicAdd(&g_cnt, 1);
        is_last = (old == FWD_GRID - 1) ? 1 : 0;
    }
    __syncthreads();
    if (is_last) {
        __threadfence();
        __shared__ float sh[4];
        const int tid = threadIdx.x;
        float acc = 0.0f;
        for (int x = tid; x < BTOT; x += 128) acc += g_res[x];
#pragma unroll
        for (int o = 16; o > 0; o >>= 1)
            acc += __shfl_xor_sync(0xffffffffu, acc, o);
        if ((tid & 31) == 0) sh[tid >> 5] = acc;
        __syncthreads();
        if (tid == 0) {
            out[0] = (sh[0] + sh[1] + sh[2] + sh[3]) / (float)BTOT;
            g_cnt  = 0;   // reset for next graph replay
        }
    }
}

extern "C" void kernel_launch(void* const* d_in, const int* in_sizes, int n_in,
                              void* d_out, int out_size) {
    const float* feats = (const float*)d_in[0];
    const int*   tags  = (const int*)d_in[1];
    const float* trans = (const float*)d_in[2];
    float* out = (float*)d_out;

    crf_fused_kernel<<<FWD_GRID, 128>>>(feats, tags, trans, out);
}

// round 15
// speedup vs baseline: 1.0310x; 1.0310x over previous
#include <cuda_runtime.h>
#include <cstdint>

#define KTAG 64
#define BTOT 1024
#define TLEN 512
#define START_TAG 62
#define FWD_GRID (BTOT / 4)   // 256 blocks x 4 warps = 1024 rows

// Scratch (allocation-free rule: __device__ globals)
__device__ float g_res[BTOT];   // forward_score[b] - gold_score[b]
__device__ int   g_cnt = 0;

typedef unsigned long long ull;

__device__ __forceinline__ ull pk2(float x, float y) {
    return (ull)__float_as_uint(x) | ((ull)__float_as_uint(y) << 32);
}
__device__ __forceinline__ float lo2(ull v) { return __uint_as_float((unsigned)v); }
__device__ __forceinline__ float hi2(ull v) { return __uint_as_float((unsigned)(v >> 32)); }
__device__ __forceinline__ float rcpf(float x) {
    float r; asm("rcp.approx.f32 %0, %1;" : "=f"(r) : "f"(x)); return r;
}

#define FMA2(acc, a, b) asm("fma.rn.f32x2 %0, %1, %2, %0;" : "+l"(acc) : "l"(a), "l"(b))
#define ADD2(d, a, b)   asm("add.rn.f32x2 %0, %1, %2;" : "=l"(d) : "l"(a), "l"(b))
#define MUL2(d, a, b)   asm("mul.rn.f32x2 %0, %1, %2;" : "=l"(d) : "l"(a), "l"(b))

// ---------------------------------------------------------------------------
// Fully fused CRF kernel — FINAL (R13, the measured optimum of the session).
// One warp per batch row; lane l owns tags 2l, 2l+1 and their
// E = exp(transitions) rows (f32x2-packed, 124 regs). Structurally zero tag
// pair (62,63) skipped (w[62]==0 for t>=2, E[:,63]==0).
// Per step: s_i = sum_j E[i,j] w_j (16 LDS.128 + 60 FMA2, 8 chains);
// w' = s * exp(f_t), renormalized by u = w[0] every 4th step only (exact
// bookkeeping — any positive u is exact; bounded growth stays well inside
// fp32 range). 4-deep feat prefetch keeps MLP=4 so the streaming LDG is off
// the loop-carried critical path (the single biggest win of the session).
// Gold path fused: trans table in smem (dodges L1 wash by the feat stream),
// tags as uint8 in smem, feats[t][ct] shuffled from the owning lane.
// Last-block mean reduction with validated ordering:
//   g_res stores -> __threadfence (all threads) -> __syncthreads -> counter.
// ---------------------------------------------------------------------------
__global__ void __launch_bounds__(128, 2)
crf_fused_kernel(const float* __restrict__ feats,
                 const int* __restrict__ tags,
                 const float* __restrict__ trans,
                 float* __restrict__ out) {
    const int lane = threadIdx.x & 31;
    const int w    = threadIdx.x >> 5;          // row within CTA (0..3)
    const int b    = blockIdx.x * 4 + w;
    const int i0   = 2 * lane;
    const int i1   = 2 * lane + 1;

    __shared__ __align__(16) float         sw_[4][2][KTAG];
    __shared__ __align__(16) float         strans[KTAG * KTAG];   // 16 KB
    __shared__ __align__(16) unsigned char stagsu[4][TLEN];       // 2 KB

    // copy trans to smem (float4 coalesced, whole CTA)
    {
        const float4* t4 = (const float4*)trans;
        float4* s4 = (float4*)strans;
#pragma unroll
        for (int j = threadIdx.x; j < (KTAG * KTAG) / 4; j += 128) s4[j] = t4[j];
    }

    // cache this row's tags as uint8 (int4 coalesced loads)
    {
        const int4* tg4 = (const int4*)(tags + (size_t)b * TLEN);
        uchar4* st4 = (uchar4*)stagsu[w];
#pragma unroll
        for (int j = lane; j < TLEN / 4; j += 32) {
            int4 v = tg4[j];
            st4[j] = make_uchar4((unsigned char)v.x, (unsigned char)v.y,
                                 (unsigned char)v.z, (unsigned char)v.w);
        }
    }

    // E rows for tags i0, i1 (f32x2 packed over j); pair jj=31 skipped
    ull E0[31], E1[31];
#pragma unroll
    for (int jj = 0; jj < 31; jj++) {
        E0[jj] = pk2(__expf(trans[i0 * KTAG + 2 * jj]),
                     __expf(trans[i0 * KTAG + 2 * jj + 1]));
        E1[jj] = pk2(__expf(trans[i1 * KTAG + 2 * jj]),
                     __expf(trans[i1 * KTAG + 2 * jj + 1]));
    }

    const float* fb = feats + (size_t)b * TLEN * KTAG;

    // t = 1 exact: w1 = exp(trans[:,START] + feat1)
    float2 f1 = *(const float2*)(fb + 1 * KTAG + i0);
    float a0 = trans[i0 * KTAG + START_TAG] + f1.x;
    float a1 = trans[i1 * KTAG + START_TAG] + f1.y;
    *(float2*)&sw_[w][0][i0] = make_float2(__expf(a0), __expf(a1));
    float L = 0.0f;
    __syncthreads();                              // strans + stags + w1 visible

    // gold init (t = 1): trans[ct,pt] + feats[1][ct] via shfl
    int   pt = stagsu[w][0];
    float gold;
    {
        int ct = stagsu[w][1];
        float gs = (ct & 1) ? f1.y : f1.x;
        gold = strans[ct * KTAG + pt] + __shfl_sync(0xffffffffu, gs, ct >> 1);
        pt = ct;
    }

    // 4-deep feat pipeline: F[k] = feat(t = 2+k) raw
    float2 F[4];
#pragma unroll
    for (int k = 0; k < 4; k++)
        F[k] = *(const float2*)(fb + (size_t)(2 + k) * KTAG + i0);

    // gold accumulation for step T, raw feat pair (FX, FY) — all smem
#define GOLD_ACC(T, FX, FY)                                                   \
    {                                                                         \
        int ct = stagsu[w][(T)];                                              \
        float gs = (ct & 1) ? (FY) : (FX);                                    \
        gold += strans[ct * KTAG + pt];                                       \
        gold += __shfl_sync(0xffffffffu, gs, ct >> 1);                        \
        pt = ct;                                                              \
    }

    // one recurrence step; NORM = 1 -> renormalize by u = w[0]
#define STEP_BODY(T, EFC0, EFC1, NORM)                                        \
    {                                                                         \
        const int rbuf = (T) & 1;                                             \
        const ulonglong2* vp = (const ulonglong2*)sw_[w][rbuf];               \
        ulonglong2 v0 = vp[0];                                                \
        ull c0 = 0, c1 = 0, c2 = 0, c3 = 0;                                   \
        ull d0 = 0, d1 = 0, d2 = 0, d3 = 0;                                   \
        FMA2(c0, E0[0], v0.x); FMA2(c1, E0[1], v0.y);                         \
        FMA2(d0, E1[0], v0.x); FMA2(d1, E1[1], v0.y);                         \
        _Pragma("unroll")                                                     \
        for (int q = 1; q < 16; q++) {                                        \
            ulonglong2 vv = vp[q];                                            \
            if (q == 15) {            /* pair (62,63) contributes zero */     \
                FMA2(c2, E0[30], vv.x);                                       \
                FMA2(d2, E1[30], vv.x);                                       \
            } else if (q & 1) {                                               \
                FMA2(c2, E0[2 * q], vv.x); FMA2(c3, E0[2 * q + 1], vv.y);     \
                FMA2(d2, E1[2 * q], vv.x); FMA2(d3, E1[2 * q + 1], vv.y);     \
            } else {                                                          \
                FMA2(c0, E0[2 * q], vv.x); FMA2(c1, E0[2 * q + 1], vv.y);     \
                FMA2(d0, E1[2 * q], vv.x); FMA2(d1, E1[2 * q + 1], vv.y);     \
            }                                                                 \
        }                                                                     \
        ull cA, cB, cs, dA, dB, ds, sp, sq, sv2, mm, wn;                      \
        ADD2(cA, c0, c2); ADD2(cB, c1, c3); ADD2(cs, cA, cB);                 \
        ADD2(dA, d0, d2); ADD2(dB, d1, d3); ADD2(ds, dA, dB);                 \
        sp = pk2(lo2(cs), lo2(ds));                                           \
        sq = pk2(hi2(cs), hi2(ds));                                           \
        ADD2(sv2, sp, sq);                        /* (s0, s1) packed */       \
        if (NORM) {                                                           \
            float uu = lo2(v0.x);                                             \
            float r  = rcpf(uu);                                              \
            L += __logf(uu);                                                  \
            mm = pk2((EFC0) * r, (EFC1) * r);                                 \
        } else {                                                              \
            mm = pk2((EFC0), (EFC1));                                         \
        }                                                                     \
        MUL2(wn, sv2, mm);                                                    \
        *(ull*)&sw_[w][rbuf ^ 1][i0] = wn;                                    \
        __syncwarp();                                                         \
    }

    // main loop: t = 2 .. 509, 127 blocks of 4 (MLP=4); norm at k == 3
    for (int kb = 0; kb < 127; kb++) {
#pragma unroll
        for (int k = 0; k < 4; k++) {
            const int t = 2 + 4 * kb + k;
            float fx = F[k].x, fy = F[k].y;
            GOLD_ACC(t, fx, fy)
            float efc0 = __expf(fx);
            float efc1 = __expf(fy);
            int tn = t + 4; if (tn > TLEN - 1) tn = TLEN - 1;
            F[k] = *(const float2*)(fb + (size_t)tn * KTAG + i0);
            if (k == 3) { STEP_BODY(t, efc0, efc1, 1) }
            else        { STEP_BODY(t, efc0, efc1, 0) }
        }
    }

    // t = 510 (feat in F[0])
    {
        float fx = F[0].x, fy = F[0].y;
        GOLD_ACC(510, fx, fy)
        float efc0 = __expf(fx);
        float efc1 = __expf(fy);
        STEP_BODY(510, efc0, efc1, 0)
    }

    // final step t = 511 (feat in F[1]): forward = L + log(sum_i s_i*exp(f_i))
    {
        float fx = F[1].x, fy = F[1].y;
        GOLD_ACC(511, fx, fy)
        float ef0 = __expf(fx);
        float ef1 = __expf(fy);
        const int rbuf = (TLEN - 1) & 1;
        const ulonglong2* vp = (const ulonglong2*)sw_[w][rbuf];
        ull c0 = 0, c1 = 0, c2 = 0, c3 = 0;
        ull d0 = 0, d1 = 0, d2 = 0, d3 = 0;
#pragma unroll
        for (int q = 0; q < 16; q++) {
            ulonglong2 vv = vp[q];
            if (q == 15) {
                FMA2(c2, E0[30], vv.x);
                FMA2(d2, E1[30], vv.x);
            } else if (q & 1) {
                FMA2(c2, E0[2 * q], vv.x); FMA2(c3, E0[2 * q + 1], vv.y);
                FMA2(d2, E1[2 * q], vv.x); FMA2(d3, E1[2 * q + 1], vv.y);
            } else {
                FMA2(c0, E0[2 * q], vv.x); FMA2(c1, E0[2 * q + 1], vv.y);
                FMA2(d0, E1[2 * q], vv.x); FMA2(d1, E1[2 * q + 1], vv.y);
            }
        }
        ull cA, cB, cs, dA, dB, ds;
        ADD2(cA, c0, c2); ADD2(cB, c1, c3); ADD2(cs, cA, cB);
        ADD2(dA, d0, d2); ADD2(dB, d1, d3); ADD2(ds, dA, dB);
        float s0 = lo2(cs) + hi2(cs);
        float s1 = lo2(ds) + hi2(ds);
        float z = s0 * ef0 + s1 * ef1;
#pragma unroll
        for (int o = 16; o > 0; o >>= 1)
            z += __shfl_xor_sync(0xffffffffu, z, o);
        if (lane == 0) g_res[b] = (L + __logf(z)) - gold;
    }
#undef STEP_BODY
#undef GOLD_ACC

    // ---- last-block mean reduction (validated ordering) ----
    // per-warp g_res stores -> __threadfence (every thread) -> __syncthreads
    // -> atomic counter. Counter self-resets for graph replay.
    __threadfence();
    __syncthreads();
    __shared__ int is_last;
    if (threadIdx.x == 0) {
        int old = atomicAdd(&g_cnt, 1);
        is_last = (old == FWD_GRID - 1) ? 1 : 0;
    }
    __syncthreads();
    if (is_last) {
        __threadfence();
        __shared__ float sh[4];
        const int tid = threadIdx.x;
        float acc = 0.0f;
        for (int x = tid; x < BTOT; x += 128) acc += g_res[x];
#pragma unroll
        for (int o = 16; o > 0; o >>= 1)
            acc += __shfl_xor_sync(0xffffffffu, acc, o);
        if ((tid & 31) == 0) sh[tid >> 5] = acc;
        __syncthreads();
        if (tid == 0) {
            out[0] = (sh[0] + sh[1] + sh[2] + sh[3]) / (float)BTOT;
            g_cnt  = 0;   // reset for next graph replay
        }
    }
}

extern "C" void kernel_launch(void* const* d_in, const int* in_sizes, int n_in,
                              void* d_out, int out_size) {
    const float* feats = (const float*)d_in[0];
    const int*   tags  = (const int*)d_in[1];
    const float* trans = (const float*)d_in[2];
    float* out = (float*)d_out;

    crf_fused_kernel<<<FWD_GRID, 128>>>(feats, tags, trans, out);
}

// round 16
// speedup vs baseline: 1.0642x; 1.0322x over previous
#include <cuda_runtime.h>
#include <cstdint>

#define KTAG 64
#define BTOT 1024
#define TLEN 512
#define START_TAG 62
#define FWD_GRID (BTOT / 4)   // 256 blocks x 4 warps = 1024 rows

// Scratch (allocation-free rule: __device__ globals)
__device__ float g_res[BTOT];   // forward_score[b] - gold_score[b]
__device__ int   g_cnt = 0;

typedef unsigned long long ull;

__device__ __forceinline__ ull pk2(float x, float y) {
    return (ull)__float_as_uint(x) | ((ull)__float_as_uint(y) << 32);
}
__device__ __forceinline__ float lo2(ull v) { return __uint_as_float((unsigned)v); }
__device__ __forceinline__ float hi2(ull v) { return __uint_as_float((unsigned)(v >> 32)); }
__device__ __forceinline__ float rcpf(float x) {
    float r; asm("rcp.approx.f32 %0, %1;" : "=f"(r) : "f"(x)); return r;
}

#define FMA2(acc, a, b) asm("fma.rn.f32x2 %0, %1, %2, %0;" : "+l"(acc) : "l"(a), "l"(b))
#define ADD2(d, a, b)   asm("add.rn.f32x2 %0, %1, %2;" : "=l"(d) : "l"(a), "l"(b))
#define MUL2(d, a, b)   asm("mul.rn.f32x2 %0, %1, %2;" : "=l"(d) : "l"(a), "l"(b))

// ---------------------------------------------------------------------------
// Fully fused CRF kernel (R13/R15 optimum) + 8-deep feat prefetch (MLP=8).
// One warp per batch row; lane l owns tags 2l, 2l+1 and their
// E = exp(transitions) rows (f32x2-packed, 124 regs). Structurally zero tag
// pair (62,63) skipped (w[62]==0 for t>=2, E[:,63]==0).
// Per step: s_i = sum_j E[i,j] w_j (16 LDS.128 + 60 FMA2, 8 chains);
// w' = s * exp(f_t), renormalized by u = w[0] every 4th step only (exact
// bookkeeping — any positive u is exact; bounded growth stays inside fp32).
// 8-deep feat pipeline doubles the per-load latency budget so the streaming
// LDG stays off the loop-carried path even under cross-CTA L1tex queueing.
// Gold path fused: trans table + tags(uint8) in smem, feats[t][ct] shuffled
// from the owning lane. Last-block mean reduction with validated ordering:
//   g_res stores -> __threadfence (all threads) -> __syncthreads -> counter.
// ---------------------------------------------------------------------------
__global__ void __launch_bounds__(128, 2)
crf_fused_kernel(const float* __restrict__ feats,
                 const int* __restrict__ tags,
                 const float* __restrict__ trans,
                 float* __restrict__ out) {
    const int lane = threadIdx.x & 31;
    const int w    = threadIdx.x >> 5;          // row within CTA (0..3)
    const int b    = blockIdx.x * 4 + w;
    const int i0   = 2 * lane;
    const int i1   = 2 * lane + 1;

    __shared__ __align__(16) float         sw_[4][2][KTAG];
    __shared__ __align__(16) float         strans[KTAG * KTAG];   // 16 KB
    __shared__ __align__(16) unsigned char stagsu[4][TLEN];       // 2 KB

    // copy trans to smem (float4 coalesced, whole CTA)
    {
        const float4* t4 = (const float4*)trans;
        float4* s4 = (float4*)strans;
#pragma unroll
        for (int j = threadIdx.x; j < (KTAG * KTAG) / 4; j += 128) s4[j] = t4[j];
    }

    // cache this row's tags as uint8 (int4 coalesced loads)
    {
        const int4* tg4 = (const int4*)(tags + (size_t)b * TLEN);
        uchar4* st4 = (uchar4*)stagsu[w];
#pragma unroll
        for (int j = lane; j < TLEN / 4; j += 32) {
            int4 v = tg4[j];
            st4[j] = make_uchar4((unsigned char)v.x, (unsigned char)v.y,
                                 (unsigned char)v.z, (unsigned char)v.w);
        }
    }

    // E rows for tags i0, i1 (f32x2 packed over j); pair jj=31 skipped
    ull E0[31], E1[31];
#pragma unroll
    for (int jj = 0; jj < 31; jj++) {
        E0[jj] = pk2(__expf(trans[i0 * KTAG + 2 * jj]),
                     __expf(trans[i0 * KTAG + 2 * jj + 1]));
        E1[jj] = pk2(__expf(trans[i1 * KTAG + 2 * jj]),
                     __expf(trans[i1 * KTAG + 2 * jj + 1]));
    }

    const float* fb = feats + (size_t)b * TLEN * KTAG;

    // t = 1 exact: w1 = exp(trans[:,START] + feat1)
    float2 f1 = *(const float2*)(fb + 1 * KTAG + i0);
    float a0 = trans[i0 * KTAG + START_TAG] + f1.x;
    float a1 = trans[i1 * KTAG + START_TAG] + f1.y;
    *(float2*)&sw_[w][0][i0] = make_float2(__expf(a0), __expf(a1));
    float L = 0.0f;
    __syncthreads();                              // strans + stags + w1 visible

    // gold init (t = 1): trans[ct,pt] + feats[1][ct] via shfl
    int   pt = stagsu[w][0];
    float gold;
    {
        int ct = stagsu[w][1];
        float gs = (ct & 1) ? f1.y : f1.x;
        gold = strans[ct * KTAG + pt] + __shfl_sync(0xffffffffu, gs, ct >> 1);
        pt = ct;
    }

    // 8-deep feat pipeline: F[k] = feat(t = 2+k) raw (MLP=8)
    float2 F[8];
#pragma unroll
    for (int k = 0; k < 8; k++)
        F[k] = *(const float2*)(fb + (size_t)(2 + k) * KTAG + i0);

    // gold accumulation for step T, raw feat pair (FX, FY) — all smem
#define GOLD_ACC(T, FX, FY)                                                   \
    {                                                                         \
        int ct = stagsu[w][(T)];                                              \
        float gs = (ct & 1) ? (FY) : (FX);                                    \
        gold += strans[ct * KTAG + pt];                                       \
        gold += __shfl_sync(0xffffffffu, gs, ct >> 1);                        \
        pt = ct;                                                              \
    }

    // one recurrence step; NORM = 1 -> renormalize by u = w[0]
#define STEP_BODY(T, EFC0, EFC1, NORM)                                        \
    {                                                                         \
        const int rbuf = (T) & 1;                                             \
        const ulonglong2* vp = (const ulonglong2*)sw_[w][rbuf];               \
        ulonglong2 v0 = vp[0];                                                \
        ull c0 = 0, c1 = 0, c2 = 0, c3 = 0;                                   \
        ull d0 = 0, d1 = 0, d2 = 0, d3 = 0;                                   \
        FMA2(c0, E0[0], v0.x); FMA2(c1, E0[1], v0.y);                         \
        FMA2(d0, E1[0], v0.x); FMA2(d1, E1[1], v0.y);                         \
        _Pragma("unroll")                                                     \
        for (int q = 1; q < 16; q++) {                                        \
            ulonglong2 vv = vp[q];                                            \
            if (q == 15) {            /* pair (62,63) contributes zero */     \
                FMA2(c2, E0[30], vv.x);                                       \
                FMA2(d2, E1[30], vv.x);                                       \
            } else if (q & 1) {                                               \
                FMA2(c2, E0[2 * q], vv.x); FMA2(c3, E0[2 * q + 1], vv.y);     \
                FMA2(d2, E1[2 * q], vv.x); FMA2(d3, E1[2 * q + 1], vv.y);     \
            } else {                                                          \
                FMA2(c0, E0[2 * q], vv.x); FMA2(c1, E0[2 * q + 1], vv.y);     \
                FMA2(d0, E1[2 * q], vv.x); FMA2(d1, E1[2 * q + 1], vv.y);     \
            }                                                                 \
        }                                                                     \
        ull cA, cB, cs, dA, dB, ds, sp, sq, sv2, mm, wn;                      \
        ADD2(cA, c0, c2); ADD2(cB, c1, c3); ADD2(cs, cA, cB);                 \
        ADD2(dA, d0, d2); ADD2(dB, d1, d3); ADD2(ds, dA, dB);                 \
        sp = pk2(lo2(cs), lo2(ds));                                           \
        sq = pk2(hi2(cs), hi2(ds));                                           \
        ADD2(sv2, sp, sq);                        /* (s0, s1) packed */       \
        if (NORM) {                                                           \
            float uu = lo2(v0.x);                                             \
            float r  = rcpf(uu);                                              \
            L += __logf(uu);                                                  \
            mm = pk2((EFC0) * r, (EFC1) * r);                                 \
        } else {                                                              \
            mm = pk2((EFC0), (EFC1));                                         \
        }                                                                     \
        MUL2(wn, sv2, mm);                                                    \
        *(ull*)&sw_[w][rbuf ^ 1][i0] = wn;                                    \
        __syncwarp();                                                         \
    }

    // main loop: t = 2 .. 505, 63 blocks of 8 (MLP=8); norm when t%4 == 1
    for (int kb = 0; kb < 63; kb++) {
#pragma unroll
        for (int k = 0; k < 8; k++) {
            const int t = 2 + 8 * kb + k;
            float fx = F[k].x, fy = F[k].y;
            GOLD_ACC(t, fx, fy)
            float efc0 = __expf(fx);
            float efc1 = __expf(fy);
            int tn = t + 8; if (tn > TLEN - 1) tn = TLEN - 1;
            F[k] = *(const float2*)(fb + (size_t)tn * KTAG + i0);
            // norm at t % 4 == 1 (k == 3 or k == 7): same cadence as R13
            if ((k & 3) == 3) { STEP_BODY(t, efc0, efc1, 1) }
            else              { STEP_BODY(t, efc0, efc1, 0) }
        }
    }

    // tail: t = 506 .. 510 consume F[0..4] (loaded in the last block;
    // F[k] = feat(506+k)); norm at t == 509 keeps the t%4==1 cadence
#pragma unroll
    for (int k = 0; k < 5; k++) {
        const int t = 506 + k;
        float fx = F[k].x, fy = F[k].y;
        GOLD_ACC(t, fx, fy)
        float efc0 = __expf(fx);
        float efc1 = __expf(fy);
        if (t == 509) { STEP_BODY(t, efc0, efc1, 1) }
        else          { STEP_BODY(t, efc0, efc1, 0) }
    }

    // final step t = 511 (feat in F[5]): forward = L + log(sum_i s_i*exp(f_i))
    {
        float fx = F[5].x, fy = F[5].y;
        GOLD_ACC(511, fx, fy)
        float ef0 = __expf(fx);
        float ef1 = __expf(fy);
        const int rbuf = (TLEN - 1) & 1;
        const ulonglong2* vp = (const ulonglong2*)sw_[w][rbuf];
        ull c0 = 0, c1 = 0, c2 = 0, c3 = 0;
        ull d0 = 0, d1 = 0, d2 = 0, d3 = 0;
#pragma unroll
        for (int q = 0; q < 16; q++) {
            ulonglong2 vv = vp[q];
            if (q == 15) {
                FMA2(c2, E0[30], vv.x);
                FMA2(d2, E1[30], vv.x);
            } else if (q & 1) {
                FMA2(c2, E0[2 * q], vv.x); FMA2(c3, E0[2 * q + 1], vv.y);
                FMA2(d2, E1[2 * q], vv.x); FMA2(d3, E1[2 * q + 1], vv.y);
            } else {
                FMA2(c0, E0[2 * q], vv.x); FMA2(c1, E0[2 * q + 1], vv.y);
                FMA2(d0, E1[2 * q], vv.x); FMA2(d1, E1[2 * q + 1], vv.y);
            }
        }
        ull cA, cB, cs, dA, dB, ds;
        ADD2(cA, c0, c2); ADD2(cB, c1, c3); ADD2(cs, cA, cB);
        ADD2(dA, d0, d2); ADD2(dB, d1, d3); ADD2(ds, dA, dB);
        float s0 = lo2(cs) + hi2(cs);
        float s1 = lo2(ds) + hi2(ds);
        float z = s0 * ef0 + s1 * ef1;
#pragma unroll
        for (int o = 16; o > 0; o >>= 1)
            z += __shfl_xor_sync(0xffffffffu, z, o);
        if (lane == 0) g_res[b] = (L + __logf(z)) - gold;
    }
#undef STEP_BODY
#undef GOLD_ACC

    // ---- last-block mean reduction (validated ordering) ----
    // per-warp g_res stores -> __threadfence (every thread) -> __syncthreads
    // -> atomic counter. Counter self-resets for graph replay.
    __threadfence();
    __syncthreads();
    __shared__ int is_last;
    if (threadIdx.x == 0) {
        int old = atomicAdd(&g_cnt, 1);
        is_last = (old == FWD_GRID - 1) ? 1 : 0;
    }
    __syncthreads();
    if (is_last) {
        __threadfence();
        __shared__ float sh[4];
        const int tid = threadIdx.x;
        float acc = 0.0f;
        for (int x = tid; x < BTOT; x += 128) acc += g_res[x];
#pragma unroll
        for (int o = 16; o > 0; o >>= 1)
            acc += __shfl_xor_sync(0xffffffffu, acc, o);
        if ((tid & 31) == 0) sh[tid >> 5] = acc;
        __syncthreads();
        if (tid == 0) {
            out[0] = (sh[0] + sh[1] + sh[2] + sh[3]) / (float)BTOT;
            g_cnt  = 0;   // reset for next graph replay
        }
    }
}

extern "C" void kernel_launch(void* const* d_in, const int* in_sizes, int n_in,
                              void* d_out, int out_size) {
    const float* feats = (const float*)d_in[0];
    const int*   tags  = (const int*)d_in[1];
    const float* trans = (const float*)d_in[2];
    float* out = (float*)d_out;

    crf_fused_kernel<<<FWD_GRID, 128>>>(feats, tags, trans, out);
}

// round 17
// speedup vs baseline: 1.0803x; 1.0152x over previous
#include <cuda_runtime.h>
#include <cstdint>

#define KTAG 64
#define BTOT 1024
#define TLEN 512
#define START_TAG 62
#define FWD_GRID (BTOT / 4)   // 256 blocks x 4 warps = 1024 rows

// Scratch (allocation-free rule: __device__ globals)
__device__ float g_res[BTOT];   // forward_score[b] - gold_score[b]
__device__ int   g_cnt = 0;

typedef unsigned long long ull;

__device__ __forceinline__ ull pk2(float x, float y) {
    return (ull)__float_as_uint(x) | ((ull)__float_as_uint(y) << 32);
}
__device__ __forceinline__ float lo2(ull v) { return __uint_as_float((unsigned)v); }
__device__ __forceinline__ float hi2(ull v) { return __uint_as_float((unsigned)(v >> 32)); }
__device__ __forceinline__ float rcpf(float x) {
    float r; asm("rcp.approx.f32 %0, %1;" : "=f"(r) : "f"(x)); return r;
}

#define FMA2(acc, a, b) asm("fma.rn.f32x2 %0, %1, %2, %0;" : "+l"(acc) : "l"(a), "l"(b))
#define ADD2(d, a, b)   asm("add.rn.f32x2 %0, %1, %2;" : "=l"(d) : "l"(a), "l"(b))
#define MUL2(d, a, b)   asm("mul.rn.f32x2 %0, %1, %2;" : "=l"(d) : "l"(a), "l"(b))

// ---------------------------------------------------------------------------
// Fully fused CRF kernel (R16 base) with 16-deep feat prefetch (MLP=16).
// R16 (MLP=8) confirmed residual LDG-latency exposure under cross-CTA L1tex
// queueing (161.2 -> 156.1 us); this doubles the per-load budget again
// (~9.6K cyc), decisively covering any queue-inflated DRAM latency.
// One warp per batch row; lane l owns tags 2l, 2l+1 and their
// E = exp(transitions) rows (f32x2-packed, 124 regs). Structurally zero tag
// pair (62,63) skipped. Per step: s_i = sum_j E[i,j] w_j (16 LDS.128 +
// 60 FMA2, 8 chains); w' = s * exp(f_t), renormalized by u = w[0] every 4th
// step only (exact bookkeeping). Gold path fused (trans + uint8 tags in
// smem, feat term shuffled from owning lane). Last-block mean reduction
// with validated ordering (stores -> fence -> syncthreads -> counter).
// ---------------------------------------------------------------------------
__global__ void __launch_bounds__(128, 2)
crf_fused_kernel(const float* __restrict__ feats,
                 const int* __restrict__ tags,
                 const float* __restrict__ trans,
                 float* __restrict__ out) {
    const int lane = threadIdx.x & 31;
    const int w    = threadIdx.x >> 5;          // row within CTA (0..3)
    const int b    = blockIdx.x * 4 + w;
    const int i0   = 2 * lane;
    const int i1   = 2 * lane + 1;

    __shared__ __align__(16) float         sw_[4][2][KTAG];
    __shared__ __align__(16) float         strans[KTAG * KTAG];   // 16 KB
    __shared__ __align__(16) unsigned char stagsu[4][TLEN];       // 2 KB

    // copy trans to smem (float4 coalesced, whole CTA)
    {
        const float4* t4 = (const float4*)trans;
        float4* s4 = (float4*)strans;
#pragma unroll
        for (int j = threadIdx.x; j < (KTAG * KTAG) / 4; j += 128) s4[j] = t4[j];
    }

    // cache this row's tags as uint8 (int4 coalesced loads)
    {
        const int4* tg4 = (const int4*)(tags + (size_t)b * TLEN);
        uchar4* st4 = (uchar4*)stagsu[w];
#pragma unroll
        for (int j = lane; j < TLEN / 4; j += 32) {
            int4 v = tg4[j];
            st4[j] = make_uchar4((unsigned char)v.x, (unsigned char)v.y,
                                 (unsigned char)v.z, (unsigned char)v.w);
        }
    }

    // E rows for tags i0, i1 (f32x2 packed over j); pair jj=31 skipped
    ull E0[31], E1[31];
#pragma unroll
    for (int jj = 0; jj < 31; jj++) {
        E0[jj] = pk2(__expf(trans[i0 * KTAG + 2 * jj]),
                     __expf(trans[i0 * KTAG + 2 * jj + 1]));
        E1[jj] = pk2(__expf(trans[i1 * KTAG + 2 * jj]),
                     __expf(trans[i1 * KTAG + 2 * jj + 1]));
    }

    const float* fb = feats + (size_t)b * TLEN * KTAG;

    // t = 1 exact: w1 = exp(trans[:,START] + feat1)
    float2 f1 = *(const float2*)(fb + 1 * KTAG + i0);
    float a0 = trans[i0 * KTAG + START_TAG] + f1.x;
    float a1 = trans[i1 * KTAG + START_TAG] + f1.y;
    *(float2*)&sw_[w][0][i0] = make_float2(__expf(a0), __expf(a1));
    float L = 0.0f;
    __syncthreads();                              // strans + stags + w1 visible

    // gold init (t = 1): trans[ct,pt] + feats[1][ct] via shfl
    int   pt = stagsu[w][0];
    float gold;
    {
        int ct = stagsu[w][1];
        float gs = (ct & 1) ? f1.y : f1.x;
        gold = strans[ct * KTAG + pt] + __shfl_sync(0xffffffffu, gs, ct >> 1);
        pt = ct;
    }

    // 16-deep feat pipeline: F[k] = feat(t = 2+k) raw (MLP=16)
    float2 F[16];
#pragma unroll
    for (int k = 0; k < 16; k++)
        F[k] = *(const float2*)(fb + (size_t)(2 + k) * KTAG + i0);

    // gold accumulation for step T, raw feat pair (FX, FY) — all smem
#define GOLD_ACC(T, FX, FY)                                                   \
    {                                                                         \
        int ct = stagsu[w][(T)];                                              \
        float gs = (ct & 1) ? (FY) : (FX);                                    \
        gold += strans[ct * KTAG + pt];                                       \
        gold += __shfl_sync(0xffffffffu, gs, ct >> 1);                        \
        pt = ct;                                                              \
    }

    // one recurrence step; NORM = 1 -> renormalize by u = w[0]
#define STEP_BODY(T, EFC0, EFC1, NORM)                                        \
    {                                                                         \
        const int rbuf = (T) & 1;                                             \
        const ulonglong2* vp = (const ulonglong2*)sw_[w][rbuf];               \
        ulonglong2 v0 = vp[0];                                                \
        ull c0 = 0, c1 = 0, c2 = 0, c3 = 0;                                   \
        ull d0 = 0, d1 = 0, d2 = 0, d3 = 0;                                   \
        FMA2(c0, E0[0], v0.x); FMA2(c1, E0[1], v0.y);                         \
        FMA2(d0, E1[0], v0.x); FMA2(d1, E1[1], v0.y);                         \
        _Pragma("unroll")                                                     \
        for (int q = 1; q < 16; q++) {                                        \
            ulonglong2 vv = vp[q];                                            \
            if (q == 15) {            /* pair (62,63) contributes zero */     \
                FMA2(c2, E0[30], vv.x);                                       \
                FMA2(d2, E1[30], vv.x);                                       \
            } else if (q & 1) {                                               \
                FMA2(c2, E0[2 * q], vv.x); FMA2(c3, E0[2 * q + 1], vv.y);     \
                FMA2(d2, E1[2 * q], vv.x); FMA2(d3, E1[2 * q + 1], vv.y);     \
            } else {                                                          \
                FMA2(c0, E0[2 * q], vv.x); FMA2(c1, E0[2 * q + 1], vv.y);     \
                FMA2(d0, E1[2 * q], vv.x); FMA2(d1, E1[2 * q + 1], vv.y);     \
            }                                                                 \
        }                                                                     \
        ull cA, cB, cs, dA, dB, ds, sp, sq, sv2, mm, wn;                      \
        ADD2(cA, c0, c2); ADD2(cB, c1, c3); ADD2(cs, cA, cB);                 \
        ADD2(dA, d0, d2); ADD2(dB, d1, d3); ADD2(ds, dA, dB);                 \
        sp = pk2(lo2(cs), lo2(ds));                                           \
        sq = pk2(hi2(cs), hi2(ds));                                           \
        ADD2(sv2, sp, sq);                        /* (s0, s1) packed */       \
        if (NORM) {                                                           \
            float uu = lo2(v0.x);                                             \
            float r  = rcpf(uu);                                              \
            L += __logf(uu);                                                  \
            mm = pk2((EFC0) * r, (EFC1) * r);                                 \
        } else {                                                              \
            mm = pk2((EFC0), (EFC1));                                         \
        }                                                                     \
        MUL2(wn, sv2, mm);                                                    \
        *(ull*)&sw_[w][rbuf ^ 1][i0] = wn;                                    \
        __syncwarp();                                                         \
    }

    // main loop: t = 2 .. 497, 31 blocks of 16 (MLP=16); norm when t%4 == 1
    for (int kb = 0; kb < 31; kb++) {
#pragma unroll
        for (int k = 0; k < 16; k++) {
            const int t = 2 + 16 * kb + k;
            float fx = F[k].x, fy = F[k].y;
            GOLD_ACC(t, fx, fy)
            float efc0 = __expf(fx);
            float efc1 = __expf(fy);
            int tn = t + 16; if (tn > TLEN - 1) tn = TLEN - 1;
            F[k] = *(const float2*)(fb + (size_t)tn * KTAG + i0);
            // norm at t % 4 == 1  <=>  k % 4 == 3 (t = 2 + 16kb + k)
            if ((k & 3) == 3) { STEP_BODY(t, efc0, efc1, 1) }
            else              { STEP_BODY(t, efc0, efc1, 0) }
        }
    }

    // tail: t = 498 .. 510 consume F[0..12] (F[k] = feat(498+k));
    // norm at t = 501, 505, 509 (k = 3, 7, 11) keeps the t%4==1 cadence
#pragma unroll
    for (int k = 0; k < 13; k++) {
        const int t = 498 + k;
        float fx = F[k].x, fy = F[k].y;
        GOLD_ACC(t, fx, fy)
        float efc0 = __expf(fx);
        float efc1 = __expf(fy);
        if ((k & 3) == 3) { STEP_BODY(t, efc0, efc1, 1) }
        else              { STEP_BODY(t, efc0, efc1, 0) }
    }

    // final step t = 511 (feat in F[13]): forward = L + log(sum_i s_i*exp(f_i))
    {
        float fx = F[13].x, fy = F[13].y;
        GOLD_ACC(511, fx, fy)
        float ef0 = __expf(fx);
        float ef1 = __expf(fy);
        const int rbuf = (TLEN - 1) & 1;
        const ulonglong2* vp = (const ulonglong2*)sw_[w][rbuf];
        ull c0 = 0, c1 = 0, c2 = 0, c3 = 0;
        ull d0 = 0, d1 = 0, d2 = 0, d3 = 0;
#pragma unroll
        for (int q = 0; q < 16; q++) {
            ulonglong2 vv = vp[q];
            if (q == 15) {
                FMA2(c2, E0[30], vv.x);
                FMA2(d2, E1[30], vv.x);
            } else if (q & 1) {
                FMA2(c2, E0[2 * q], vv.x); FMA2(c3, E0[2 * q + 1], vv.y);
                FMA2(d2, E1[2 * q], vv.x); FMA2(d3, E1[2 * q + 1], vv.y);
            } else {
                FMA2(c0, E0[2 * q], vv.x); FMA2(c1, E0[2 * q + 1], vv.y);
                FMA2(d0, E1[2 * q], vv.x); FMA2(d1, E1[2 * q + 1], vv.y);
            }
        }
        ull cA, cB, cs, dA, dB, ds;
        ADD2(cA, c0, c2); ADD2(cB, c1, c3); ADD2(cs, cA, cB);
        ADD2(dA, d0, d2); ADD2(dB, d1, d3); ADD2(ds, dA, dB);
        float s0 = lo2(cs) + hi2(cs);
        float s1 = lo2(ds) + hi2(ds);
        float z = s0 * ef0 + s1 * ef1;
#pragma unroll
        for (int o = 16; o > 0; o >>= 1)
            z += __shfl_xor_sync(0xffffffffu, z, o);
        if (lane == 0) g_res[b] = (L + __logf(z)) - gold;
    }
#undef STEP_BODY
#undef GOLD_ACC

    // ---- last-block mean reduction (validated ordering) ----
    // per-warp g_res stores -> __threadfence (every thread) -> __syncthreads
    // -> atomic counter. Counter self-resets for graph replay.
    __threadfence();
    __syncthreads();
    __shared__ int is_last;
    if (threadIdx.x == 0) {
        int old = atomicAdd(&g_cnt, 1);
        is_last = (old == FWD_GRID - 1) ? 1 : 0;
    }
    __syncthreads();
    if (is_last) {
        __threadfence();
        __shared__ float sh[4];
        const int tid = threadIdx.x;
        float acc = 0.0f;
        for (int x = tid; x < BTOT; x += 128) acc += g_res[x];
#pragma unroll
        for (int o = 16; o > 0; o >>= 1)
            acc += __shfl_xor_sync(0xffffffffu, acc, o);
        if ((tid & 31) == 0) sh[tid >> 5] = acc;
        __syncthreads();
        if (tid == 0) {
            out[0] = (sh[0] + sh[1] + sh[2] + sh[3]) / (float)BTOT;
            g_cnt  = 0;   // reset for next graph replay
        }
    }
}

extern "C" void kernel_launch(void* const* d_in, const int* in_sizes, int n_in,
                              void* d_out, int out_size) {
    const float* feats = (const float*)d_in[0];
    const int*   tags  = (const int*)d_in[1];
    const float* trans = (const float*)d_in[2];
    float* out = (float*)d_out;

    crf_fused_kernel<<<FWD_GRID, 128>>>(feats, tags, trans, out);
}